// round 1
// baseline (speedup 1.0000x reference)
#include <cuda_runtime.h>
#include <cstdint>
#include <cstddef>

#define N    8192
#define FIN  512
#define FOUT 256
#define ITILE 64
#define JT    32

// Scratch (no cudaMalloc allowed)
__device__ float g_h[N * FOUT];        // 8 MB, h = X @ W
__device__ float g_Wa1[FIN], g_Wa2[FIN];
__device__ float g_f2[N], g_nf1[N];
__device__ float g_E1p[N], g_E1n[N], g_E2p[N], g_E2n[N];

typedef unsigned long long ull;

__device__ __forceinline__ ull pk2(float lo, float hi) {
    ull r; asm("mov.b64 %0, {%1,%2};" : "=l"(r) : "f"(lo), "f"(hi)); return r;
}
__device__ __forceinline__ void upk2(ull v, float& lo, float& hi) {
    asm("mov.b64 {%0,%1}, %2;" : "=f"(lo), "=f"(hi) : "l"(v));
}
__device__ __forceinline__ ull fma2(ull a, ull b, ull c) {
    ull d; asm("fma.rn.f32x2 %0, %1, %2, %3;" : "=l"(d) : "l"(a), "l"(b), "l"(c)); return d;
}

// ---------------------------------------------------------------------------
// Kernel 1: Wa1 = W @ a1, Wa2 = W @ a2   (one warp per row of W)
// grid = FIN/8 = 64 blocks, 256 threads
// ---------------------------------------------------------------------------
__global__ void k_wa(const float* __restrict__ W,
                     const float* __restrict__ a1,
                     const float* __restrict__ a2) {
    __shared__ float a1s[FOUT], a2s[FOUT];
    int tid = threadIdx.x;
    if (tid < FOUT) { a1s[tid] = a1[tid]; a2s[tid] = a2[tid]; }
    __syncthreads();
    int warp = tid >> 5, lane = tid & 31;
    int row = blockIdx.x * 8 + warp;
    const float* wr = W + (size_t)row * FOUT;
    float s1 = 0.f, s2 = 0.f;
    for (int c = lane; c < FOUT; c += 32) {
        float w = wr[c];
        s1 += w * a1s[c];
        s2 += w * a2s[c];
    }
    #pragma unroll
    for (int o = 16; o; o >>= 1) {
        s1 += __shfl_down_sync(0xFFFFFFFFu, s1, o);
        s2 += __shfl_down_sync(0xFFFFFFFFu, s2, o);
    }
    if (lane == 0) { g_Wa1[row] = s1; g_Wa2[row] = s2; }
}

// ---------------------------------------------------------------------------
// Kernel 2: f1 = X@Wa1, f2 = X@Wa2, plus the 4 factored exp vectors.
// grid = N/8 = 1024 blocks, 256 threads (one warp per row of X)
// ---------------------------------------------------------------------------
__global__ void k_f(const float* __restrict__ X) {
    __shared__ float wa1[FIN], wa2[FIN];
    int tid = threadIdx.x;
    for (int c = tid; c < FIN; c += 256) { wa1[c] = g_Wa1[c]; wa2[c] = g_Wa2[c]; }
    __syncthreads();
    int warp = tid >> 5, lane = tid & 31;
    int row = blockIdx.x * 8 + warp;
    const float* xr = X + (size_t)row * FIN;
    float s1 = 0.f, s2 = 0.f;
    for (int c = lane; c < FIN; c += 32) {
        float x = xr[c];
        s1 += x * wa1[c];
        s2 += x * wa2[c];
    }
    #pragma unroll
    for (int o = 16; o; o >>= 1) {
        s1 += __shfl_down_sync(0xFFFFFFFFu, s1, o);
        s2 += __shfl_down_sync(0xFFFFFFFFu, s2, o);
    }
    if (lane == 0) {
        g_nf1[row] = -s1;
        g_f2[row]  = s2;
        g_E1p[row] = expf(s1);
        g_E1n[row] = expf(0.2f * s1);
        g_E2p[row] = expf(s2);
        g_E2n[row] = expf(0.2f * s2);
    }
}

// ---------------------------------------------------------------------------
// Kernel 3: h = X @ W  (fp32 tiled GEMM, f32x2 FMAs)
// grid = (N/64, FOUT/64) = (128, 4), 256 threads (16x16), thread tile 4x4
// ---------------------------------------------------------------------------
__global__ __launch_bounds__(256) void k_gemm(const float* __restrict__ X,
                                              const float* __restrict__ W) {
    __shared__ float Xs[64][17];   // [BM][BK+1] pad to dodge bank conflicts
    __shared__ float Ws[16][64];   // [BK][BN]
    int tid = threadIdx.x;
    int tx = tid & 15, ty = tid >> 4;
    int i0 = blockIdx.x * 64, n0 = blockIdx.y * 64;

    ull acc[4][2];
    #pragma unroll
    for (int qi = 0; qi < 4; qi++)
        for (int p = 0; p < 2; p++) acc[qi][p] = pk2(0.f, 0.f);

    for (int k0 = 0; k0 < FIN; k0 += 16) {
        {   // X tile: 64x16
            int c = tid & 15, r0 = tid >> 4;
            #pragma unroll
            for (int q = 0; q < 4; q++) {
                int r = r0 + 16 * q;
                Xs[r][c] = X[(size_t)(i0 + r) * FIN + k0 + c];
            }
        }
        {   // W tile: 16x64
            int c = tid & 63, r0 = tid >> 6;
            #pragma unroll
            for (int q = 0; q < 4; q++) {
                int r = r0 + 4 * q;
                Ws[r][c] = W[(size_t)(k0 + r) * FOUT + n0 + c];
            }
        }
        __syncthreads();
        #pragma unroll
        for (int k = 0; k < 16; k++) {
            float a_[4], b_[4];
            #pragma unroll
            for (int q = 0; q < 4; q++) a_[q] = Xs[ty * 4 + q][k];
            #pragma unroll
            for (int q = 0; q < 4; q++) b_[q] = Ws[k][tx * 4 + q];
            ull b20 = pk2(b_[0], b_[1]);
            ull b21 = pk2(b_[2], b_[3]);
            #pragma unroll
            for (int qi = 0; qi < 4; qi++) {
                ull av = pk2(a_[qi], a_[qi]);
                acc[qi][0] = fma2(av, b20, acc[qi][0]);
                acc[qi][1] = fma2(av, b21, acc[qi][1]);
            }
        }
        __syncthreads();
    }
    #pragma unroll
    for (int qi = 0; qi < 4; qi++) {
        float v0, v1, v2, v3;
        upk2(acc[qi][0], v0, v1);
        upk2(acc[qi][1], v2, v3);
        float* dst = g_h + (size_t)(i0 + ty * 4 + qi) * FOUT + n0 + tx * 4;
        dst[0] = v0; dst[1] = v1; dst[2] = v2; dst[3] = v3;
    }
}

// ---------------------------------------------------------------------------
// Kernel 4: fused masked softmax-weighted aggregation + ELU.
//   out[i,:] = ELU( (sum_j w_ij * h[j,:]) / (sum_j w_ij) )
//   w_ij = adj_ij ? (f2_j >= -f1_i ? E1p_i*E2p_j : E1n_i*E2n_j) : 0
// grid = N/ITILE = 128 blocks (1 wave), 256 threads.
// Thread (tx,ty): 8 rows (i = ty*8+ii) x 8 features (f = tx + 32*ff).
// ---------------------------------------------------------------------------
__global__ __launch_bounds__(256, 1) void k_attn(const int* __restrict__ adj,
                                                 float* __restrict__ out) {
    __shared__ float h_s[JT][FOUT];        // 32 KB
    __shared__ float w_s[ITILE][JT];       // 8 KB
    __shared__ float f2_s[JT], e2p_s[JT], e2n_s[JT];
    __shared__ float nf1_s[ITILE], e1p_s[ITILE], e1n_s[ITILE];
    __shared__ float z_s[ITILE];

    int tid = threadIdx.x;
    int i0 = blockIdx.x * ITILE;
    if (tid < ITILE) {
        nf1_s[tid] = g_nf1[i0 + tid];
        e1p_s[tid] = g_E1p[i0 + tid];
        e1n_s[tid] = g_E1n[i0 + tid];
    }
    __syncthreads();

    const int tx = tid & 31, ty = tid >> 5;
    const int ilw = tid >> 2;          // weight-gen: i_local 0..63
    const int jlw = (tid & 3) << 3;    // weight-gen: j base {0,8,16,24}
    const float nf1w = nf1_s[ilw], e1pw = e1p_s[ilw], e1nw = e1n_s[ilw];
    const int hr = tid >> 3;           // h-load row 0..31
    const int hc = (tid & 7) * 8;      // h-load float4 base

    ull acc[8][4];
    #pragma unroll
    for (int ii = 0; ii < 8; ii++)
        for (int p = 0; p < 4; p++) acc[ii][p] = pk2(0.f, 0.f);
    float zacc = 0.f;

    for (int j0 = 0; j0 < N; j0 += JT) {
        // --- global loads (h chunk, f2 chunk, adj tile) ---
        if (tid < JT) {
            f2_s[tid]  = g_f2[j0 + tid];
            e2p_s[tid] = g_E2p[j0 + tid];
            e2n_s[tid] = g_E2n[j0 + tid];
        }
        {
            const float4* src = (const float4*)(g_h + (size_t)(j0 + hr) * FOUT);
            float4* dst = (float4*)&h_s[hr][0];
            #pragma unroll
            for (int q = 0; q < 8; q++) dst[hc + q] = src[hc + q];
        }
        const int4* ap = (const int4*)(adj + (size_t)(i0 + ilw) * N + j0 + jlw);
        int4 av0 = ap[0], av1 = ap[1];
        __syncthreads();   // f2_s ready

        // --- weight tile generation (factored exp) ---
        {
            int av[8] = {av0.x, av0.y, av0.z, av0.w, av1.x, av1.y, av1.z, av1.w};
            float wv[8];
            #pragma unroll
            for (int k = 0; k < 8; k++) {
                int j = jlw + k;
                float w = (f2_s[j] >= nf1w) ? e1pw * e2p_s[j] : e1nw * e2n_s[j];
                wv[k] = av[k] ? w : 0.f;
            }
            float4* wd = (float4*)&w_s[ilw][jlw];
            wd[0] = make_float4(wv[0], wv[1], wv[2], wv[3]);
            wd[1] = make_float4(wv[4], wv[5], wv[6], wv[7]);
        }
        __syncthreads();   // w_s + h_s ready

        // --- main accumulation: acc[i][f] += w[i][j] * h[j][f]  (f32x2) ---
        #pragma unroll 4
        for (int jl = 0; jl < JT; jl++) {
            ull h2[4];
            #pragma unroll
            for (int p = 0; p < 4; p++)
                h2[p] = pk2(h_s[jl][tx + 64 * p], h_s[jl][tx + 64 * p + 32]);
            #pragma unroll
            for (int ii = 0; ii < 8; ii++) {
                float w = w_s[ty * 8 + ii][jl];   // warp-uniform broadcast
                ull w2 = pk2(w, w);
                #pragma unroll
                for (int p = 0; p < 4; p++)
                    acc[ii][p] = fma2(w2, h2[p], acc[ii][p]);
            }
        }
        // --- row-sum Z (threads 0..63, rotated index: conflict-free) ---
        if (tid < ITILE) {
            #pragma unroll
            for (int t = 0; t < JT; t++) {
                int jl = (tid + t) & (JT - 1);
                zacc += w_s[tid][jl];
            }
        }
        __syncthreads();   // all consumed; safe to overwrite next chunk
    }

    if (tid < ITILE) z_s[tid] = zacc;
    __syncthreads();

    // --- epilogue: normalize + ELU ---
    #pragma unroll
    for (int ii = 0; ii < 8; ii++) {
        int i = i0 + ty * 8 + ii;
        float inv = 1.f / z_s[ty * 8 + ii];
        float* orow = out + (size_t)i * FOUT;
        #pragma unroll
        for (int p = 0; p < 4; p++) {
            float lo, hi;
            upk2(acc[ii][p], lo, hi);
            lo *= inv; hi *= inv;
            orow[tx + 64 * p]      = (lo > 0.f) ? lo : expm1f(lo);
            orow[tx + 64 * p + 32] = (hi > 0.f) ? hi : expm1f(hi);
        }
    }
}

// ---------------------------------------------------------------------------
extern "C" void kernel_launch(void* const* d_in, const int* in_sizes, int n_in,
                              void* d_out, int out_size) {
    (void)in_sizes; (void)n_in; (void)out_size;
    const float* X   = (const float*)d_in[0];
    const int*   adj = (const int*)d_in[1];
    const float* W   = (const float*)d_in[2];
    const float* a1  = (const float*)d_in[3];
    const float* a2  = (const float*)d_in[4];
    float* out = (float*)d_out;

    k_wa<<<FIN / 8, 256>>>(W, a1, a2);
    k_f<<<N / 8, 256>>>(X);
    k_gemm<<<dim3(N / 64, FOUT / 64), 256>>>(X, W);
    k_attn<<<N / ITILE, 256>>>(adj, out);
}

// round 2
// speedup vs baseline: 1.0010x; 1.0010x over previous
#include <cuda_runtime.h>
#include <cstdint>
#include <cstddef>

#define N    8192
#define FIN  512
#define FOUT 256
#define ITILE 64
#define JT    32

// Scratch (no cudaMalloc allowed)
__device__ float g_h[N * FOUT];        // 8 MB, h = X @ W
__device__ float g_Wa1[FIN], g_Wa2[FIN];
__device__ float g_f2[N], g_nf1[N];
__device__ float g_E1p[N], g_E1n[N], g_E2p[N], g_E2n[N];

typedef unsigned long long ull;

__device__ __forceinline__ ull pk2(float lo, float hi) {
    ull r; asm("mov.b64 %0, {%1,%2};" : "=l"(r) : "f"(lo), "f"(hi)); return r;
}
__device__ __forceinline__ void upk2(ull v, float& lo, float& hi) {
    asm("mov.b64 {%0,%1}, %2;" : "=f"(lo), "=f"(hi) : "l"(v));
}
__device__ __forceinline__ ull fma2(ull a, ull b, ull c) {
    ull d; asm("fma.rn.f32x2 %0, %1, %2, %3;" : "=l"(d) : "l"(a), "l"(b), "l"(c)); return d;
}

// ---------------------------------------------------------------------------
// Kernel 1: Wa1 = W @ a1, Wa2 = W @ a2   (one warp per row of W)
// grid = FIN/8 = 64 blocks, 256 threads
// ---------------------------------------------------------------------------
__global__ void k_wa(const float* __restrict__ W,
                     const float* __restrict__ a1,
                     const float* __restrict__ a2) {
    __shared__ float a1s[FOUT], a2s[FOUT];
    int tid = threadIdx.x;
    if (tid < FOUT) { a1s[tid] = a1[tid]; a2s[tid] = a2[tid]; }
    __syncthreads();
    int warp = tid >> 5, lane = tid & 31;
    int row = blockIdx.x * 8 + warp;
    const float* wr = W + (size_t)row * FOUT;
    float s1 = 0.f, s2 = 0.f;
    for (int c = lane; c < FOUT; c += 32) {
        float w = wr[c];
        s1 += w * a1s[c];
        s2 += w * a2s[c];
    }
    #pragma unroll
    for (int o = 16; o; o >>= 1) {
        s1 += __shfl_down_sync(0xFFFFFFFFu, s1, o);
        s2 += __shfl_down_sync(0xFFFFFFFFu, s2, o);
    }
    if (lane == 0) { g_Wa1[row] = s1; g_Wa2[row] = s2; }
}

// ---------------------------------------------------------------------------
// Kernel 2: f1 = X@Wa1, f2 = X@Wa2, plus the 4 factored exp vectors.
// grid = N/8 = 1024 blocks, 256 threads (one warp per row of X)
// ---------------------------------------------------------------------------
__global__ void k_f(const float* __restrict__ X) {
    __shared__ float wa1[FIN], wa2[FIN];
    int tid = threadIdx.x;
    for (int c = tid; c < FIN; c += 256) { wa1[c] = g_Wa1[c]; wa2[c] = g_Wa2[c]; }
    __syncthreads();
    int warp = tid >> 5, lane = tid & 31;
    int row = blockIdx.x * 8 + warp;
    const float* xr = X + (size_t)row * FIN;
    float s1 = 0.f, s2 = 0.f;
    for (int c = lane; c < FIN; c += 32) {
        float x = xr[c];
        s1 += x * wa1[c];
        s2 += x * wa2[c];
    }
    #pragma unroll
    for (int o = 16; o; o >>= 1) {
        s1 += __shfl_down_sync(0xFFFFFFFFu, s1, o);
        s2 += __shfl_down_sync(0xFFFFFFFFu, s2, o);
    }
    if (lane == 0) {
        g_nf1[row] = -s1;
        g_f2[row]  = s2;
        g_E1p[row] = expf(s1);
        g_E1n[row] = expf(0.2f * s1);
        g_E2p[row] = expf(s2);
        g_E2n[row] = expf(0.2f * s2);
    }
}

// ---------------------------------------------------------------------------
// Kernel 3: h = X @ W  (fp32 tiled GEMM, f32x2 FMAs)
// grid = (N/64, FOUT/64) = (128, 4), 256 threads (16x16), thread tile 4x4
// ---------------------------------------------------------------------------
__global__ __launch_bounds__(256) void k_gemm(const float* __restrict__ X,
                                              const float* __restrict__ W) {
    __shared__ float Xs[64][17];   // [BM][BK+1] pad to dodge bank conflicts
    __shared__ float Ws[16][64];   // [BK][BN]
    int tid = threadIdx.x;
    int tx = tid & 15, ty = tid >> 4;
    int i0 = blockIdx.x * 64, n0 = blockIdx.y * 64;

    ull acc[4][2];
    #pragma unroll
    for (int qi = 0; qi < 4; qi++)
        for (int p = 0; p < 2; p++) acc[qi][p] = pk2(0.f, 0.f);

    for (int k0 = 0; k0 < FIN; k0 += 16) {
        {   // X tile: 64x16
            int c = tid & 15, r0 = tid >> 4;
            #pragma unroll
            for (int q = 0; q < 4; q++) {
                int r = r0 + 16 * q;
                Xs[r][c] = X[(size_t)(i0 + r) * FIN + k0 + c];
            }
        }
        {   // W tile: 16x64
            int c = tid & 63, r0 = tid >> 6;
            #pragma unroll
            for (int q = 0; q < 4; q++) {
                int r = r0 + 4 * q;
                Ws[r][c] = W[(size_t)(k0 + r) * FOUT + n0 + c];
            }
        }
        __syncthreads();
        #pragma unroll
        for (int k = 0; k < 16; k++) {
            float a_[4], b_[4];
            #pragma unroll
            for (int q = 0; q < 4; q++) a_[q] = Xs[ty * 4 + q][k];
            #pragma unroll
            for (int q = 0; q < 4; q++) b_[q] = Ws[k][tx * 4 + q];
            ull b20 = pk2(b_[0], b_[1]);
            ull b21 = pk2(b_[2], b_[3]);
            #pragma unroll
            for (int qi = 0; qi < 4; qi++) {
                ull av = pk2(a_[qi], a_[qi]);
                acc[qi][0] = fma2(av, b20, acc[qi][0]);
                acc[qi][1] = fma2(av, b21, acc[qi][1]);
            }
        }
        __syncthreads();
    }
    #pragma unroll
    for (int qi = 0; qi < 4; qi++) {
        float v0, v1, v2, v3;
        upk2(acc[qi][0], v0, v1);
        upk2(acc[qi][1], v2, v3);
        float* dst = g_h + (size_t)(i0 + ty * 4 + qi) * FOUT + n0 + tx * 4;
        dst[0] = v0; dst[1] = v1; dst[2] = v2; dst[3] = v3;
    }
}

// ---------------------------------------------------------------------------
// Kernel 4: fused masked softmax-weighted aggregation + ELU.
//   out[i,:] = ELU( (sum_j w_ij * h[j,:]) / (sum_j w_ij) )
//   w_ij = adj_ij ? (f2_j >= -f1_i ? E1p_i*E2p_j : E1n_i*E2n_j) : 0
// grid = N/ITILE = 128 blocks (1 wave), 256 threads.
// Thread (tx,ty): 8 rows (i = ty*8+ii) x 8 features (f = tx + 32*ff).
// ---------------------------------------------------------------------------
__global__ __launch_bounds__(256, 1) void k_attn(const int* __restrict__ adj,
                                                 float* __restrict__ out) {
    __shared__ float h_s[JT][FOUT];        // 32 KB
    __shared__ float w_s[ITILE][JT];       // 8 KB
    __shared__ float f2_s[JT], e2p_s[JT], e2n_s[JT];
    __shared__ float nf1_s[ITILE], e1p_s[ITILE], e1n_s[ITILE];
    __shared__ float z_s[ITILE];

    int tid = threadIdx.x;
    int i0 = blockIdx.x * ITILE;
    if (tid < ITILE) {
        nf1_s[tid] = g_nf1[i0 + tid];
        e1p_s[tid] = g_E1p[i0 + tid];
        e1n_s[tid] = g_E1n[i0 + tid];
    }
    __syncthreads();

    const int tx = tid & 31, ty = tid >> 5;
    const int ilw = tid >> 2;          // weight-gen: i_local 0..63
    const int jlw = (tid & 3) << 3;    // weight-gen: j base {0,8,16,24}
    const float nf1w = nf1_s[ilw], e1pw = e1p_s[ilw], e1nw = e1n_s[ilw];
    const int hr = tid >> 3;           // h-load row 0..31
    const int hc = (tid & 7) * 8;      // h-load float4 base

    ull acc[8][4];
    #pragma unroll
    for (int ii = 0; ii < 8; ii++)
        for (int p = 0; p < 4; p++) acc[ii][p] = pk2(0.f, 0.f);
    float zacc = 0.f;

    for (int j0 = 0; j0 < N; j0 += JT) {
        // --- global loads (h chunk, f2 chunk, adj tile) ---
        if (tid < JT) {
            f2_s[tid]  = g_f2[j0 + tid];
            e2p_s[tid] = g_E2p[j0 + tid];
            e2n_s[tid] = g_E2n[j0 + tid];
        }
        {
            const float4* src = (const float4*)(g_h + (size_t)(j0 + hr) * FOUT);
            float4* dst = (float4*)&h_s[hr][0];
            #pragma unroll
            for (int q = 0; q < 8; q++) dst[hc + q] = src[hc + q];
        }
        const int4* ap = (const int4*)(adj + (size_t)(i0 + ilw) * N + j0 + jlw);
        int4 av0 = ap[0], av1 = ap[1];
        __syncthreads();   // f2_s ready

        // --- weight tile generation (factored exp) ---
        {
            int av[8] = {av0.x, av0.y, av0.z, av0.w, av1.x, av1.y, av1.z, av1.w};
            float wv[8];
            #pragma unroll
            for (int k = 0; k < 8; k++) {
                int j = jlw + k;
                float w = (f2_s[j] >= nf1w) ? e1pw * e2p_s[j] : e1nw * e2n_s[j];
                wv[k] = av[k] ? w : 0.f;
            }
            float4* wd = (float4*)&w_s[ilw][jlw];
            wd[0] = make_float4(wv[0], wv[1], wv[2], wv[3]);
            wd[1] = make_float4(wv[4], wv[5], wv[6], wv[7]);
        }
        __syncthreads();   // w_s + h_s ready

        // --- main accumulation: acc[i][f] += w[i][j] * h[j][f]  (f32x2) ---
        #pragma unroll 4
        for (int jl = 0; jl < JT; jl++) {
            ull h2[4];
            #pragma unroll
            for (int p = 0; p < 4; p++)
                h2[p] = pk2(h_s[jl][tx + 64 * p], h_s[jl][tx + 64 * p + 32]);
            #pragma unroll
            for (int ii = 0; ii < 8; ii++) {
                float w = w_s[ty * 8 + ii][jl];   // warp-uniform broadcast
                ull w2 = pk2(w, w);
                #pragma unroll
                for (int p = 0; p < 4; p++)
                    acc[ii][p] = fma2(w2, h2[p], acc[ii][p]);
            }
        }
        // --- row-sum Z (threads 0..63, rotated index: conflict-free) ---
        if (tid < ITILE) {
            #pragma unroll
            for (int t = 0; t < JT; t++) {
                int jl = (tid + t) & (JT - 1);
                zacc += w_s[tid][jl];
            }
        }
        __syncthreads();   // all consumed; safe to overwrite next chunk
    }

    if (tid < ITILE) z_s[tid] = zacc;
    __syncthreads();

    // --- epilogue: normalize + ELU ---
    #pragma unroll
    for (int ii = 0; ii < 8; ii++) {
        int i = i0 + ty * 8 + ii;
        float inv = 1.f / z_s[ty * 8 + ii];
        float* orow = out + (size_t)i * FOUT;
        #pragma unroll
        for (int p = 0; p < 4; p++) {
            float lo, hi;
            upk2(acc[ii][p], lo, hi);
            lo *= inv; hi *= inv;
            orow[tx + 64 * p]      = (lo > 0.f) ? lo : expm1f(lo);
            orow[tx + 64 * p + 32] = (hi > 0.f) ? hi : expm1f(hi);
        }
    }
}

// ---------------------------------------------------------------------------
extern "C" void kernel_launch(void* const* d_in, const int* in_sizes, int n_in,
                              void* d_out, int out_size) {
    (void)in_sizes; (void)n_in; (void)out_size;
    const float* X   = (const float*)d_in[0];
    const int*   adj = (const int*)d_in[1];
    const float* W   = (const float*)d_in[2];
    const float* a1  = (const float*)d_in[3];
    const float* a2  = (const float*)d_in[4];
    float* out = (float*)d_out;

    k_wa<<<FIN / 8, 256>>>(W, a1, a2);
    k_f<<<N / 8, 256>>>(X);
    k_gemm<<<dim3(N / 64, FOUT / 64), 256>>>(X, W);
    k_attn<<<N / ITILE, 256>>>(adj, out);
}

// round 5
// speedup vs baseline: 2.4120x; 2.4096x over previous
#include <cuda_runtime.h>
#include <cuda_bf16.h>
#include <cstdint>
#include <cstddef>

#define N    8192
#define FIN  512
#define FOUT 256
#define JT     64                 // j per chunk
#define SPLITS 2
#define JHALF  (N / SPLITS)       // 4096
#define NCHUNK (JHALF / JT)       // 64

// ---------------- scratch (no cudaMalloc allowed) ----------------
__device__ __nv_bfloat16 g_hT_hi[FOUT * N];   // 4 MB  h^T high bf16  [f][i]
__device__ __nv_bfloat16 g_hT_lo[FOUT * N];   // 4 MB  h^T low  bf16
__device__ float  g_Wa1[FIN], g_Wa2[FIN];
__device__ float4 g_ivec[N];                  // (-f1, e^{f1}, e^{0.2 f1}, 0)
__device__ float4 g_jvec[N];                  // ( f2, e^{f2}, e^{0.2 f2}, 0)
__device__ float  g_pnum[128 * 128 * 256];    // partial numerators (16.8 MB)
__device__ float  g_pz[128 * 128];            // partial Z

typedef unsigned long long ull;

// ---------------- PTX helpers (all baseline sm_80+, legal at .target sm_100) --
__device__ __forceinline__ uint32_t smem_u32(const void* p) {
    uint32_t a;
    asm("{ .reg .u64 t; cvta.to.shared.u64 t, %1; cvt.u32.u64 %0, t; }" : "=r"(a) : "l"(p));
    return a;
}
#define CP_ASYNC16(dst, src) \
    asm volatile("cp.async.cg.shared.global [%0], [%1], 16;" :: "r"((uint32_t)(dst)), "l"(src) : "memory")
#define CP_COMMIT() asm volatile("cp.async.commit_group;" ::: "memory")
#define CP_WAIT0()  asm volatile("cp.async.wait_group 0;" ::: "memory")

__device__ __forceinline__ void ldsm4(uint32_t* r, uint32_t addr) {
    asm volatile("ldmatrix.sync.aligned.m8n8.x4.shared.b16 {%0,%1,%2,%3}, [%4];"
        : "=r"(r[0]), "=r"(r[1]), "=r"(r[2]), "=r"(r[3]) : "r"(addr));
}
__device__ __forceinline__ void mma16816(float* d, const uint32_t* a, uint32_t b0, uint32_t b1) {
    asm volatile("mma.sync.aligned.m16n8k16.row.col.f32.bf16.bf16.f32 "
        "{%0,%1,%2,%3}, {%4,%5,%6,%7}, {%8,%9}, {%0,%1,%2,%3};"
        : "+f"(d[0]), "+f"(d[1]), "+f"(d[2]), "+f"(d[3])
        : "r"(a[0]), "r"(a[1]), "r"(a[2]), "r"(a[3]), "r"(b0), "r"(b1));
}

__device__ __forceinline__ ull pk2(float lo, float hi) {
    ull r; asm("mov.b64 %0, {%1,%2};" : "=l"(r) : "f"(lo), "f"(hi)); return r;
}
__device__ __forceinline__ void upk2(ull v, float& lo, float& hi) {
    asm("mov.b64 {%0,%1}, %2;" : "=f"(lo), "=f"(hi) : "l"(v));
}
__device__ __forceinline__ ull fma2(ull a, ull b, ull c) {
    ull d; asm("fma.rn.f32x2 %0, %1, %2, %3;" : "=l"(d) : "l"(a), "l"(b), "l"(c)); return d;
}
__device__ __forceinline__ uint32_t sw128(uint32_t off) { return off ^ ((off >> 3) & 0x70); }

// ---------------------------------------------------------------------------
// Kernel 1: Wa1 = W @ a1, Wa2 = W @ a2
// ---------------------------------------------------------------------------
__global__ void k_wa(const float* __restrict__ W,
                     const float* __restrict__ a1,
                     const float* __restrict__ a2) {
    __shared__ float a1s[FOUT], a2s[FOUT];
    int tid = threadIdx.x;
    if (tid < FOUT) { a1s[tid] = a1[tid]; a2s[tid] = a2[tid]; }
    __syncthreads();
    int warp = tid >> 5, lane = tid & 31;
    int row = blockIdx.x * 8 + warp;
    const float* wr = W + (size_t)row * FOUT;
    float s1 = 0.f, s2 = 0.f;
    for (int c = lane; c < FOUT; c += 32) {
        float w = wr[c];
        s1 += w * a1s[c];
        s2 += w * a2s[c];
    }
    #pragma unroll
    for (int o = 16; o; o >>= 1) {
        s1 += __shfl_down_sync(0xFFFFFFFFu, s1, o);
        s2 += __shfl_down_sync(0xFFFFFFFFu, s2, o);
    }
    if (lane == 0) { g_Wa1[row] = s1; g_Wa2[row] = s2; }
}

// ---------------------------------------------------------------------------
// Kernel 2: exact fp32 logits f1,f2 + packed factored-exp vectors
// ---------------------------------------------------------------------------
__global__ void k_f(const float* __restrict__ X) {
    __shared__ float wa1[FIN], wa2[FIN];
    int tid = threadIdx.x;
    for (int c = tid; c < FIN; c += 256) { wa1[c] = g_Wa1[c]; wa2[c] = g_Wa2[c]; }
    __syncthreads();
    int warp = tid >> 5, lane = tid & 31;
    int row = blockIdx.x * 8 + warp;
    const float* xr = X + (size_t)row * FIN;
    float s1 = 0.f, s2 = 0.f;
    for (int c = lane; c < FIN; c += 32) {
        float x = xr[c];
        s1 += x * wa1[c];
        s2 += x * wa2[c];
    }
    #pragma unroll
    for (int o = 16; o; o >>= 1) {
        s1 += __shfl_down_sync(0xFFFFFFFFu, s1, o);
        s2 += __shfl_down_sync(0xFFFFFFFFu, s2, o);
    }
    if (lane == 0) {
        g_ivec[row] = make_float4(-s1, expf(s1), expf(0.2f * s1), 0.f);
        g_jvec[row] = make_float4(s2, expf(s2), expf(0.2f * s2), 0.f);
    }
}

// ---------------------------------------------------------------------------
// Kernel 3: h = X @ W (fp32), output TRANSPOSED as bf16 hi/lo: g_hT[f][i]
// ---------------------------------------------------------------------------
__global__ __launch_bounds__(256) void k_gemm(const float* __restrict__ X,
                                              const float* __restrict__ W) {
    __shared__ float Xs[64][17];
    __shared__ float Ws[16][64];
    __shared__ float Ts[64][65];   // transpose staging [f_local][i_local]
    int tid = threadIdx.x;
    int tx = tid & 15, ty = tid >> 4;
    int i0 = blockIdx.x * 64, n0 = blockIdx.y * 64;

    ull acc[4][2];
    #pragma unroll
    for (int qi = 0; qi < 4; qi++)
        for (int p = 0; p < 2; p++) acc[qi][p] = pk2(0.f, 0.f);

    for (int k0 = 0; k0 < FIN; k0 += 16) {
        {
            int c = tid & 15, r0 = tid >> 4;
            #pragma unroll
            for (int q = 0; q < 4; q++) {
                int r = r0 + 16 * q;
                Xs[r][c] = X[(size_t)(i0 + r) * FIN + k0 + c];
            }
        }
        {
            int c = tid & 63, r0 = tid >> 6;
            #pragma unroll
            for (int q = 0; q < 4; q++) {
                int r = r0 + 4 * q;
                Ws[r][c] = W[(size_t)(k0 + r) * FOUT + n0 + c];
            }
        }
        __syncthreads();
        #pragma unroll
        for (int k = 0; k < 16; k++) {
            float a_[4], b_[4];
            #pragma unroll
            for (int q = 0; q < 4; q++) a_[q] = Xs[ty * 4 + q][k];
            #pragma unroll
            for (int q = 0; q < 4; q++) b_[q] = Ws[k][tx * 4 + q];
            ull b20 = pk2(b_[0], b_[1]);
            ull b21 = pk2(b_[2], b_[3]);
            #pragma unroll
            for (int qi = 0; qi < 4; qi++) {
                ull av = pk2(a_[qi], a_[qi]);
                acc[qi][0] = fma2(av, b20, acc[qi][0]);
                acc[qi][1] = fma2(av, b21, acc[qi][1]);
            }
        }
        __syncthreads();
    }
    #pragma unroll
    for (int qi = 0; qi < 4; qi++) {
        float v0, v1, v2, v3;
        upk2(acc[qi][0], v0, v1);
        upk2(acc[qi][1], v2, v3);
        int il = ty * 4 + qi;
        Ts[tx * 4 + 0][il] = v0;
        Ts[tx * 4 + 1][il] = v1;
        Ts[tx * 4 + 2][il] = v2;
        Ts[tx * 4 + 3][il] = v3;
    }
    __syncthreads();
    {
        int fl = tid >> 2, ib = (tid & 3) * 16;
        __nv_bfloat16 hb[16], lb[16];
        #pragma unroll
        for (int k = 0; k < 16; k++) {
            float v = Ts[fl][ib + k];
            __nv_bfloat16 h = __float2bfloat16(v);
            hb[k] = h;
            lb[k] = __float2bfloat16(v - __bfloat162float(h));
        }
        size_t base = (size_t)(n0 + fl) * N + i0 + ib;
        *(uint4*)(g_hT_hi + base)     = *(uint4*)&hb[0];
        *(uint4*)(g_hT_hi + base + 8) = *(uint4*)&hb[8];
        *(uint4*)(g_hT_lo + base)     = *(uint4*)&lb[0];
        *(uint4*)(g_hT_lo + base + 8) = *(uint4*)&lb[8];
    }
}

// ---------------------------------------------------------------------------
// Kernel 4: masked-softmax aggregation on tensor cores via mma.sync (HMMA).
// grid = 128 (64 i-tiles x 2 j-splits), 256 threads = 8 warps, 1 CTA/SM.
// Warp w owns rows [w*16, w*16+16) x all 256 f; acc = 128 fp32 regs/thread.
// Per 64-j chunk: 3 bf16 chains (AhiBhi, AhiBlo, AloBhi) = 384 mma/warp.
// Double-buffered smem; B via cp.async, A generated in-kernel. Z SIMT.
// ---------------------------------------------------------------------------
#define OFF_BUF  1024
#define STAGE_BYTES 98304            // Ahi 16K | Alo 16K | Bhi 32K | Blo 32K
#define OFF_AHI(s) (OFF_BUF + (s) * STAGE_BYTES)
#define OFF_ALO(s) (OFF_AHI(s) + 16384)
#define OFF_BHI(s) (OFF_AHI(s) + 32768)
#define OFF_BLO(s) (OFF_AHI(s) + 65536)
#define SMEM_ATTN (OFF_BUF + 2 * STAGE_BYTES)   // 197632 bytes

__global__ __launch_bounds__(256, 1) void k_attn(const int* __restrict__ adj) {
    extern __shared__ char smem[];
    const uint32_t sb = smem_u32(smem);
    const int tid = threadIdx.x;
    const int bx = blockIdx.x;
    const int i_tile = bx >> 1, split = bx & 1;
    const int i0 = i_tile * 128;
    const int jbase = split * JHALF;

    const int warp = tid >> 5, lane = tid & 31;
    const int gr = lane >> 3, lr = lane & 7;
    // ldmatrix lane geometry
    const int a_row = warp * 16 + lr + (gr & 1) * 8;   // A row this lane addresses
    const int a_koff = (gr >> 1) * 8;                  // A col sub-offset
    const int b_roff = lr + (gr >> 1) * 8;             // B row sub-offset (within f0)
    const int b_koff = (gr & 1) * 8;                   // B col sub-offset

    // weight-gen geometry (unchanged from SIMT version)
    const int il = tid >> 1;             // i row generated (0..127)
    const int jb = (tid & 1) * 32;       // 32-wide j half
    const float4 iv = g_ivec[i0 + il];
    float zacc = 0.f;

    float acc[128];
    #pragma unroll
    for (int q = 0; q < 128; q++) acc[q] = 0.f;

    // ---- fill helpers (inlined lambdas) ----
    auto fillB = [&](int s, int jglob) {
        const __nv_bfloat16* srch = g_hT_hi + (size_t)tid * N + jglob;
        const __nv_bfloat16* srcl = g_hT_lo + (size_t)tid * N + jglob;
        #pragma unroll
        for (int q = 0; q < 8; q++) {
            uint32_t sw = sw128(tid * 128 + q * 16);
            CP_ASYNC16(sb + OFF_BHI(s) + sw, srch + q * 8);
            CP_ASYNC16(sb + OFF_BLO(s) + sw, srcl + q * 8);
        }
    };
    auto genA = [&](int s, int jglob) {
        const int4* ap = (const int4*)(adj + (size_t)(i0 + il) * N + jglob + jb);
        #pragma unroll
        for (int g = 0; g < 4; g++) {     // 8 j -> one uint4 hi + one lo
            int4 a0 = ap[2 * g], a1 = ap[2 * g + 1];
            int am[8] = {a0.x, a0.y, a0.z, a0.w, a1.x, a1.y, a1.z, a1.w};
            uint32_t phv[4], plv[4];
            #pragma unroll
            for (int p = 0; p < 4; p++) {
                float w[2];
                #pragma unroll
                for (int e = 0; e < 2; e++) {
                    int jj = g * 8 + p * 2 + e;
                    float4 jv = g_jvec[jglob + jb + jj];
                    float wv = (jv.x >= iv.x) ? iv.y * jv.y : iv.z * jv.z;
                    wv = am[p * 2 + e] ? wv : 0.f;
                    zacc += wv;
                    w[e] = wv;
                }
                __nv_bfloat162 hb = __floats2bfloat162_rn(w[0], w[1]);
                float r0 = w[0] - __low2float(hb);
                float r1 = w[1] - __high2float(hb);
                __nv_bfloat162 lb = __floats2bfloat162_rn(r0, r1);
                phv[p] = *(uint32_t*)&hb;
                plv[p] = *(uint32_t*)&lb;
            }
            uint32_t sw = sw128((uint32_t)(il * 128 + (jb + g * 8) * 2));
            *(uint4*)(smem + OFF_AHI(s) + sw) = make_uint4(phv[0], phv[1], phv[2], phv[3]);
            *(uint4*)(smem + OFF_ALO(s) + sw) = make_uint4(plv[0], plv[1], plv[2], plv[3]);
        }
    };

    // ---- prologue: chunk 0 into buffer 0 ----
    fillB(0, jbase);
    CP_COMMIT();
    genA(0, jbase);
    CP_WAIT0();
    __syncthreads();

    // ---- main loop ----
    for (int c = 0; c < NCHUNK; c++) {
        const int s = c & 1;
        if (c + 1 < NCHUNK) {
            fillB(s ^ 1, jbase + (c + 1) * JT);
            CP_COMMIT();
            genA(s ^ 1, jbase + (c + 1) * JT);
        }
        // ---- MMA over buffer s: 4 ksteps x 16 f-pairs x 3 chains ----
        #pragma unroll
        for (int k0 = 0; k0 < JT; k0 += 16) {
            uint32_t Ahi[4], Alo[4];
            uint32_t aoff = sw128((uint32_t)(a_row * 128 + (k0 + a_koff) * 2));
            ldsm4(Ahi, sb + OFF_AHI(s) + aoff);
            ldsm4(Alo, sb + OFF_ALO(s) + aoff);
            #pragma unroll
            for (int nb16 = 0; nb16 < 16; nb16++) {
                uint32_t boff = sw128((uint32_t)((nb16 * 16 + b_roff) * 128 + (k0 + b_koff) * 2));
                uint32_t Bh[4], Bl[4];
                ldsm4(Bh, sb + OFF_BHI(s) + boff);
                ldsm4(Bl, sb + OFF_BLO(s) + boff);
                float* d0 = acc + nb16 * 8;
                float* d1 = acc + nb16 * 8 + 4;
                mma16816(d0, Ahi, Bh[0], Bh[1]);
                mma16816(d1, Ahi, Bh[2], Bh[3]);
                mma16816(d0, Ahi, Bl[0], Bl[1]);
                mma16816(d1, Ahi, Bl[2], Bl[3]);
                mma16816(d0, Alo, Bh[0], Bh[1]);
                mma16816(d1, Alo, Bh[2], Bh[3]);
            }
        }
        if (c + 1 < NCHUNK) CP_WAIT0();
        __syncthreads();
    }

    // ---- Z partial ----
    {
        float ztot = zacc + __shfl_xor_sync(0xFFFFFFFFu, zacc, 1);
        if ((tid & 1) == 0) g_pz[bx * 128 + il] = ztot;
    }

    // ---- register accumulators -> gmem partial numerators ----
    // thread lane: d0=(qr,2qc) d1=(qr,2qc+1) d2=(qr+8,2qc) d3=(qr+8,2qc+1)
    {
        const int qr = lane >> 2, qc = lane & 3;
        float* base0 = g_pnum + (size_t)bx * 32768 + (size_t)(warp * 16 + qr) * 256 + 2 * qc;
        float* base1 = base0 + 8 * 256;
        #pragma unroll
        for (int nb = 0; nb < 32; nb++) {
            *(float2*)(base0 + nb * 8) = make_float2(acc[nb * 4 + 0], acc[nb * 4 + 1]);
            *(float2*)(base1 + nb * 8) = make_float2(acc[nb * 4 + 2], acc[nb * 4 + 3]);
        }
    }
}

// ---------------------------------------------------------------------------
// Kernel 5: combine splits, normalize, ELU
// ---------------------------------------------------------------------------
__global__ __launch_bounds__(256) void k_comb(float* __restrict__ out) {
    int gid = blockIdx.x * 256 + threadIdx.x;   // float4 index
    int i = gid >> 6;
    int c4 = (gid & 63) * 4;
    int it = i >> 7, row = i & 127;
    size_t b0 = (size_t)(it * 2) * 32768 + (size_t)row * 256 + c4;
    float4 n0 = *(const float4*)(g_pnum + b0);
    float4 n1 = *(const float4*)(g_pnum + b0 + 32768);
    float z = g_pz[(it * 2) * 128 + row] + g_pz[(it * 2 + 1) * 128 + row];
    float inv = 1.f / z;
    float v0 = (n0.x + n1.x) * inv;
    float v1 = (n0.y + n1.y) * inv;
    float v2 = (n0.z + n1.z) * inv;
    float v3 = (n0.w + n1.w) * inv;
    float4 o;
    o.x = (v0 > 0.f) ? v0 : expm1f(v0);
    o.y = (v1 > 0.f) ? v1 : expm1f(v1);
    o.z = (v2 > 0.f) ? v2 : expm1f(v2);
    o.w = (v3 > 0.f) ? v3 : expm1f(v3);
    *(float4*)(out + (size_t)i * FOUT + c4) = o;
}

// ---------------------------------------------------------------------------
extern "C" void kernel_launch(void* const* d_in, const int* in_sizes, int n_in,
                              void* d_out, int out_size) {
    (void)in_sizes; (void)n_in; (void)out_size;
    const float* X   = (const float*)d_in[0];
    const int*   adj = (const int*)d_in[1];
    const float* W   = (const float*)d_in[2];
    const float* a1  = (const float*)d_in[3];
    const float* a2  = (const float*)d_in[4];
    float* out = (float*)d_out;

    cudaFuncSetAttribute(k_attn, cudaFuncAttributeMaxDynamicSharedMemorySize, SMEM_ATTN);

    k_wa<<<FIN / 8, 256>>>(W, a1, a2);
    k_f<<<N / 8, 256>>>(X);
    k_gemm<<<dim3(N / 64, FOUT / 64), 256>>>(X, W);
    k_attn<<<128, 256, SMEM_ATTN>>>(adj);
    k_comb<<<(N * FOUT / 4) / 256, 256>>>(out);
}